// round 1
// baseline (speedup 1.0000x reference)
#include <cuda_runtime.h>
#include <cuda_bf16.h>
#include <cstddef>

// Problem constants
#define B_SZ   16
#define S_SZ   16
#define H_SZ   16
#define HD     64
#define D_MODEL 1024
#define PAST   4096
#define L_TOT  4112          // PAST + S
#define M_ROWS 256           // B*S

// Output layout offsets (floats): y | k | v
#define OUT_Y_OFF 0
#define OUT_K_OFF (256*1024)                     // 262144
#define OUT_V_OFF (OUT_K_OFF + 256*4112*64)      // 262144 + 67371008

// Scratch (device globals; no allocations allowed)
__device__ float g_qkv [M_ROWS * 3 * D_MODEL];   // [256, 3072]
__device__ float g_obuf[M_ROWS * D_MODEL];       // [256, 1024] = o in [B,S,H*hd]

// ---------------------------------------------------------------------------
// GEMM: C[M,N] = A[M,K] @ W[N,K]^T + bias[N]   (all row-major, fp32)
// Block tile 64x64, K-step 16, 256 threads, 4x4 microtile per thread.
// ---------------------------------------------------------------------------
__global__ __launch_bounds__(256)
void gemm_bias_kernel(const float* __restrict__ A, const float* __restrict__ W,
                      const float* __restrict__ bias, float* __restrict__ C,
                      int N, int K) {
    __shared__ float As[16][68];
    __shared__ float Bs[16][68];

    const int tid = threadIdx.x;
    const int tx = tid & 15;          // 0..15 (n micro)
    const int ty = tid >> 4;          // 0..15 (m micro)
    const int m0 = blockIdx.y * 64;
    const int n0 = blockIdx.x * 64;

    const int lr = tid >> 2;          // 0..63  tile row for loads
    const int lk = (tid & 3) * 4;     // 0,4,8,12 k offset for loads

    float c[4][4] = {};

    for (int k0 = 0; k0 < K; k0 += 16) {
        float4 a4 = *(const float4*)&A[(size_t)(m0 + lr) * K + k0 + lk];
        float4 b4 = *(const float4*)&W[(size_t)(n0 + lr) * K + k0 + lk];
        As[lk + 0][lr] = a4.x; As[lk + 1][lr] = a4.y;
        As[lk + 2][lr] = a4.z; As[lk + 3][lr] = a4.w;
        Bs[lk + 0][lr] = b4.x; Bs[lk + 1][lr] = b4.y;
        Bs[lk + 2][lr] = b4.z; Bs[lk + 3][lr] = b4.w;
        __syncthreads();

        #pragma unroll
        for (int kk = 0; kk < 16; kk++) {
            float4 av = *(const float4*)&As[kk][ty * 4];
            float4 bv = *(const float4*)&Bs[kk][tx * 4];
            c[0][0] += av.x * bv.x; c[0][1] += av.x * bv.y;
            c[0][2] += av.x * bv.z; c[0][3] += av.x * bv.w;
            c[1][0] += av.y * bv.x; c[1][1] += av.y * bv.y;
            c[1][2] += av.y * bv.z; c[1][3] += av.y * bv.w;
            c[2][0] += av.z * bv.x; c[2][1] += av.z * bv.y;
            c[2][2] += av.z * bv.z; c[2][3] += av.z * bv.w;
            c[3][0] += av.w * bv.x; c[3][1] += av.w * bv.y;
            c[3][2] += av.w * bv.z; c[3][3] += av.w * bv.w;
        }
        __syncthreads();
    }

    float4 bb = *(const float4*)&bias[n0 + tx * 4];
    #pragma unroll
    for (int i = 0; i < 4; i++) {
        float4 r = make_float4(c[i][0] + bb.x, c[i][1] + bb.y,
                               c[i][2] + bb.z, c[i][3] + bb.w);
        *(float4*)&C[(size_t)(m0 + ty * 4 + i) * N + n0 + tx * 4] = r;
    }
}

// ---------------------------------------------------------------------------
// Copy KV cache into output (re-laid out for the 4112-length concat).
// cache: [B,H,4096,64] contiguous; dst rows stride 4112*64.
// 16,777,216 float4 per tensor.
// ---------------------------------------------------------------------------
__global__ __launch_bounds__(256)
void copy_cache_kernel(const float4* __restrict__ ck, const float4* __restrict__ cv,
                       float4* __restrict__ Kd, float4* __restrict__ Vd) {
    const unsigned i = blockIdx.x * 256u + threadIdx.x;   // < 16,777,216
    const unsigned bh  = i >> 16;                          // / (4096*64/4)
    const unsigned rem = i & 65535u;
    const size_t dst = (size_t)bh * 65792u + rem;          // 4112*64/4
    Kd[dst] = ck[i];
    Vd[dst] = cv[i];
}

// ---------------------------------------------------------------------------
// Scatter the freshly projected K/V rows into positions [4096, 4112).
// 65536 float4 per tensor.
// ---------------------------------------------------------------------------
__global__ __launch_bounds__(256)
void scatter_newkv_kernel(float* __restrict__ Kd, float* __restrict__ Vd) {
    const unsigned i = blockIdx.x * 256u + threadIdx.x;    // < 65536
    const unsigned c = i & 15u;          // hd/4
    const unsigned s = (i >> 4) & 15u;
    const unsigned h = (i >> 8) & 15u;
    const unsigned b = i >> 12;
    const size_t qoff = (size_t)(b * 16 + s) * 3072 + h * 64 + c * 4;
    const size_t doff = ((size_t)(b * 16 + h) * L_TOT + PAST + s) * 64 + c * 4;
    *(float4*)&Kd[doff] = *(const float4*)&g_qkv[qoff + 1024];
    *(float4*)&Vd[doff] = *(const float4*)&g_qkv[qoff + 2048];
}

// ---------------------------------------------------------------------------
// Attention: one block per (b,h). 256 threads. Flash-style online softmax.
// Tiles of 64 rows of K/V staged through SMEM. Output o -> g_obuf [B,S,H*hd].
// ---------------------------------------------------------------------------
__global__ __launch_bounds__(256)
void attn_kernel(const float* __restrict__ Kc, const float* __restrict__ Vc) {
    __shared__ float qs[16][68];
    __shared__ float kt[64][68];
    __shared__ float vt[64][68];
    __shared__ float pt[64][17];
    __shared__ float m_run[16], l_run[16], mcur[16], fac[16];

    const int tid = threadIdx.x;
    const int b = blockIdx.x >> 4;
    const int h = blockIdx.x & 15;

    // Load q (pre-scaled by 1/sqrt(hd) = 0.125)
    {
        const int q = tid >> 4, c4 = tid & 15;
        float4 qv = *(const float4*)&g_qkv[(size_t)(b * 16 + q) * 3072 + h * 64 + c4 * 4];
        qs[q][c4 * 4 + 0] = qv.x * 0.125f;
        qs[q][c4 * 4 + 1] = qv.y * 0.125f;
        qs[q][c4 * 4 + 2] = qv.z * 0.125f;
        qs[q][c4 * 4 + 3] = qv.w * 0.125f;
    }
    if (tid < 16) { m_run[tid] = -1e30f; l_run[tid] = 0.0f; }

    const size_t base = (size_t)blockIdx.x * (L_TOT * 64);
    const float* Kb = Kc + base;
    const float* Vb = Vc + base;

    const int row4 = tid >> 2, qg = tid & 3;   // score phase mapping
    const int pq = tid >> 4, dc = tid & 15;    // AV phase mapping

    float4 oacc = make_float4(0.f, 0.f, 0.f, 0.f);

    const int nTiles = (L_TOT + 63) / 64;      // 65
    for (int t = 0; t < nTiles; t++) {
        const int l0 = t * 64;
        __syncthreads();   // previous tile fully consumed (also covers q load)

        // Stage K/V tile
        #pragma unroll
        for (int i = 0; i < 4; i++) {
            int idx = i * 256 + tid;
            int r = idx >> 4, c = idx & 15;
            int gl = l0 + r;
            if (gl < L_TOT) {
                float4 k4 = *(const float4*)&Kb[(size_t)gl * 64 + c * 4];
                float4 v4 = *(const float4*)&Vb[(size_t)gl * 64 + c * 4];
                *(float4*)&kt[r][c * 4] = k4;
                *(float4*)&vt[r][c * 4] = v4;
            }
        }
        __syncthreads();

        // Scores: thread handles (row4, queries qg*4..qg*4+3)
        {
            float a0 = 0.f, a1 = 0.f, a2 = 0.f, a3 = 0.f;
            const int gl = l0 + row4;
            if (gl < L_TOT) {
                #pragma unroll
                for (int c = 0; c < 16; c++) {
                    float4 k4 = *(const float4*)&kt[row4][c * 4];
                    float4 q0 = *(const float4*)&qs[qg * 4 + 0][c * 4];
                    float4 q1 = *(const float4*)&qs[qg * 4 + 1][c * 4];
                    float4 q2 = *(const float4*)&qs[qg * 4 + 2][c * 4];
                    float4 q3 = *(const float4*)&qs[qg * 4 + 3][c * 4];
                    a0 += k4.x*q0.x + k4.y*q0.y + k4.z*q0.z + k4.w*q0.w;
                    a1 += k4.x*q1.x + k4.y*q1.y + k4.z*q1.z + k4.w*q1.w;
                    a2 += k4.x*q2.x + k4.y*q2.y + k4.z*q2.z + k4.w*q2.w;
                    a3 += k4.x*q3.x + k4.y*q3.y + k4.z*q3.z + k4.w*q3.w;
                }
            } else {
                a0 = a1 = a2 = a3 = -1e30f;
            }
            pt[row4][qg * 4 + 0] = a0;
            pt[row4][qg * 4 + 1] = a1;
            pt[row4][qg * 4 + 2] = a2;
            pt[row4][qg * 4 + 3] = a3;
        }
        __syncthreads();

        // Per-query tile max -> running max + rescale factor
        if (tid < 16) {
            float mt = -1e30f;
            #pragma unroll 8
            for (int r = 0; r < 64; r++) mt = fmaxf(mt, pt[r][tid]);
            float mo = m_run[tid];
            float mn = fmaxf(mo, mt);
            mcur[tid] = mn;
            fac[tid]  = __expf(mo - mn);
            m_run[tid] = mn;
        }
        __syncthreads();

        // Rescale accumulators + exponentiate scores in place
        {
            float f = fac[pq];
            oacc.x *= f; oacc.y *= f; oacc.z *= f; oacc.w *= f;
            #pragma unroll
            for (int e = tid; e < 1024; e += 256) {
                int r = e >> 4, q = e & 15;
                pt[r][q] = __expf(pt[r][q] - mcur[q]);
            }
        }
        __syncthreads();

        // Row-sum for l (16 threads) runs concurrently with AV accumulation
        if (tid < 16) {
            float s = 0.f;
            #pragma unroll 8
            for (int r = 0; r < 64; r++) s += pt[r][tid];
            l_run[tid] = l_run[tid] * fac[tid] + s;
        }

        // AV: thread (pq, dc) accumulates float4 of output dims dc*4..dc*4+3
        #pragma unroll 4
        for (int r = 0; r < 64; r++) {
            float w = pt[r][pq];
            float4 v4 = *(const float4*)&vt[r][dc * 4];
            oacc.x += w * v4.x; oacc.y += w * v4.y;
            oacc.z += w * v4.z; oacc.w += w * v4.w;
        }
    }

    __syncthreads();
    const float inv = 1.0f / l_run[pq];
    float4 o = make_float4(oacc.x * inv, oacc.y * inv, oacc.z * inv, oacc.w * inv);
    // o layout: [B, S, H*hd]; row = b*16 + s(=pq), col = h*64 + dc*4
    *(float4*)&g_obuf[(size_t)(b * 16 + pq) * D_MODEL + h * 64 + dc * 4] = o;
}

// ---------------------------------------------------------------------------
extern "C" void kernel_launch(void* const* d_in, const int* in_sizes, int n_in,
                              void* d_out, int out_size) {
    const float* x       = (const float*)d_in[0];
    const float* cache_k = (const float*)d_in[1];
    const float* cache_v = (const float*)d_in[2];
    const float* qkv_w   = (const float*)d_in[3];
    const float* qkv_b   = (const float*)d_in[4];
    const float* out_w   = (const float*)d_in[5];
    const float* out_b   = (const float*)d_in[6];

    float* out   = (float*)d_out;
    float* out_y = out + OUT_Y_OFF;
    float* out_k = out + OUT_K_OFF;
    float* out_v = out + OUT_V_OFF;

    float *qkv_p = nullptr, *obuf_p = nullptr;
    cudaGetSymbolAddress((void**)&qkv_p,  g_qkv);
    cudaGetSymbolAddress((void**)&obuf_p, g_obuf);

    // 1) QKV projection: [256,1024] @ [3072,1024]^T + b -> g_qkv [256,3072]
    gemm_bias_kernel<<<dim3(3072 / 64, M_ROWS / 64), 256>>>(
        x, qkv_w, qkv_b, qkv_p, 3072, D_MODEL);

    // 2) Stream KV cache into output layout (independent of 1, but same stream)
    copy_cache_kernel<<<65536, 256>>>(
        (const float4*)cache_k, (const float4*)cache_v,
        (float4*)out_k, (float4*)out_v);

    // 3) Append new K/V rows (needs 1)
    scatter_newkv_kernel<<<256, 256>>>(out_k, out_v);

    // 4) Attention over full concatenated K/V (needs 2+3) -> g_obuf
    attn_kernel<<<B_SZ * H_SZ, 256>>>(out_k, out_v);

    // 5) Output projection: [256,1024] @ [1024,1024]^T + b -> y
    gemm_bias_kernel<<<dim3(D_MODEL / 64, M_ROWS / 64), 256>>>(
        obuf_p, out_w, out_b, out_y, D_MODEL, D_MODEL);
}

// round 2
// speedup vs baseline: 1.8667x; 1.8667x over previous
#include <cuda_runtime.h>
#include <cuda_bf16.h>
#include <cstddef>

// Problem constants
#define B_SZ    16
#define S_SZ    16
#define H_SZ    16
#define HD      64
#define D_MODEL 1024
#define PAST    4096
#define L_TOT   4112
#define M_ROWS  256
#define NSPLIT  4

// Output layout offsets (floats): y | k | v
#define OUT_Y_OFF 0
#define OUT_K_OFF (256*1024)
#define OUT_V_OFF (OUT_K_OFF + 256*4112*64)

// Scratch (device globals; no allocations allowed)
__device__ float g_qkv [M_ROWS * 3 * D_MODEL];     // [256, 3072]
__device__ float g_obuf[M_ROWS * D_MODEL];         // [256, 1024]
__device__ float g_po  [256 * NSPLIT * 16 * 64];   // per-(bh,split) partial O
__device__ float g_pm  [256 * NSPLIT * 16];        // partial max
__device__ float g_pl  [256 * NSPLIT * 16];        // partial sum

// ---------------------------------------------------------------------------
// GEMM: C[M,N] = A[M,K] @ W[N,K]^T + bias[N]   (row-major fp32)
// ---------------------------------------------------------------------------
__global__ __launch_bounds__(256)
void gemm_bias_kernel(const float* __restrict__ A, const float* __restrict__ W,
                      const float* __restrict__ bias, float* __restrict__ C,
                      int N, int K) {
    __shared__ float As[16][68];
    __shared__ float Bs[16][68];

    const int tid = threadIdx.x;
    const int tx = tid & 15;
    const int ty = tid >> 4;
    const int m0 = blockIdx.y * 64;
    const int n0 = blockIdx.x * 64;
    const int lr = tid >> 2;
    const int lk = (tid & 3) * 4;

    float c[4][4] = {};

    for (int k0 = 0; k0 < K; k0 += 16) {
        float4 a4 = *(const float4*)&A[(size_t)(m0 + lr) * K + k0 + lk];
        float4 b4 = *(const float4*)&W[(size_t)(n0 + lr) * K + k0 + lk];
        As[lk + 0][lr] = a4.x; As[lk + 1][lr] = a4.y;
        As[lk + 2][lr] = a4.z; As[lk + 3][lr] = a4.w;
        Bs[lk + 0][lr] = b4.x; Bs[lk + 1][lr] = b4.y;
        Bs[lk + 2][lr] = b4.z; Bs[lk + 3][lr] = b4.w;
        __syncthreads();

        #pragma unroll
        for (int kk = 0; kk < 16; kk++) {
            float4 av = *(const float4*)&As[kk][ty * 4];
            float4 bv = *(const float4*)&Bs[kk][tx * 4];
            c[0][0] += av.x * bv.x; c[0][1] += av.x * bv.y;
            c[0][2] += av.x * bv.z; c[0][3] += av.x * bv.w;
            c[1][0] += av.y * bv.x; c[1][1] += av.y * bv.y;
            c[1][2] += av.y * bv.z; c[1][3] += av.y * bv.w;
            c[2][0] += av.z * bv.x; c[2][1] += av.z * bv.y;
            c[2][2] += av.z * bv.z; c[2][3] += av.z * bv.w;
            c[3][0] += av.w * bv.x; c[3][1] += av.w * bv.y;
            c[3][2] += av.w * bv.z; c[3][3] += av.w * bv.w;
        }
        __syncthreads();
    }

    float4 bb = *(const float4*)&bias[n0 + tx * 4];
    #pragma unroll
    for (int i = 0; i < 4; i++) {
        float4 r = make_float4(c[i][0] + bb.x, c[i][1] + bb.y,
                               c[i][2] + bb.z, c[i][3] + bb.w);
        *(float4*)&C[(size_t)(m0 + ty * 4 + i) * N + n0 + tx * 4] = r;
    }
}

// ---------------------------------------------------------------------------
// Scatter freshly projected K/V rows into positions [4096, 4112).
// ---------------------------------------------------------------------------
__global__ __launch_bounds__(256)
void scatter_newkv_kernel(float* __restrict__ Kd, float* __restrict__ Vd) {
    const unsigned i = blockIdx.x * 256u + threadIdx.x;    // < 65536
    const unsigned c = i & 15u;
    const unsigned s = (i >> 4) & 15u;
    const unsigned h = (i >> 8) & 15u;
    const unsigned b = i >> 12;
    const size_t qoff = (size_t)(b * 16 + s) * 3072 + h * 64 + c * 4;
    const size_t doff = ((size_t)(b * 16 + h) * L_TOT + PAST + s) * 64 + c * 4;
    *(float4*)&Kd[doff] = *(const float4*)&g_qkv[qoff + 1024];
    *(float4*)&Vd[doff] = *(const float4*)&g_qkv[qoff + 2048];
}

// ---------------------------------------------------------------------------
// Fused attention + cache copy-out, split-KV.
// Grid: 1024 blocks = (bh, split). Each block handles 1024 (or 1040) KV rows
// in 64-row tiles. While loading cache tiles it also writes them to out_k/v.
// Partial (o, m, l) written to scratch; reduce kernel combines.
// ---------------------------------------------------------------------------
__global__ __launch_bounds__(256)
void attn_split_kernel(const float* __restrict__ cache_k,
                       const float* __restrict__ cache_v,
                       float* __restrict__ out_k,
                       float* __restrict__ out_v) {
    __shared__ float qs [16][68];
    __shared__ float kt [64][68];
    __shared__ float vt [64][64];
    __shared__ float ptT[16][68];
    __shared__ float m_run[16], l_run[16], fac_s[16];

    const int tid   = threadIdx.x;
    const int bh    = blockIdx.x >> 2;
    const int split = blockIdx.x & 3;
    const int b = bh >> 4, h = bh & 15;

    // Load q (pre-scaled by 1/sqrt(64))
    {
        const int q = tid >> 4, c4 = tid & 15;
        float4 qv = *(const float4*)&g_qkv[(size_t)(b * 16 + q) * 3072 + h * 64 + c4 * 4];
        qs[q][c4 * 4 + 0] = qv.x * 0.125f;
        qs[q][c4 * 4 + 1] = qv.y * 0.125f;
        qs[q][c4 * 4 + 2] = qv.z * 0.125f;
        qs[q][c4 * 4 + 3] = qv.w * 0.125f;
    }
    if (tid < 16) { m_run[tid] = -1e30f; l_run[tid] = 0.0f; }

    const int chunk0 = split * 1024;
    const int nrows  = (split == 3) ? 1040 : 1024;
    const size_t cbase = (size_t)bh * (PAST * 64);
    const size_t obase = (size_t)bh * (L_TOT * 64);

    const int qg = tid >> 6;          // score: query group 0..3
    const int kp = tid & 63;          // score: k row
    const int pq = tid >> 4;          // AV/epilogue: query
    const int dc = tid & 15;          // AV: dim group / softmax: segment

    float4 oacc = make_float4(0.f, 0.f, 0.f, 0.f);

    const int ntiles = (split == 3) ? 17 : 16;
    for (int t = 0; t < ntiles; t++) {
        const int l0   = chunk0 + t * 64;
        const int rows = min(64, chunk0 + nrows - l0);   // 64 or 16
        __syncthreads();

        // ---- stage K/V tile (fused copy-out for cache rows) ----
        #pragma unroll
        for (int i = 0; i < 4; i++) {
            int idx = i * 256 + tid;                     // 0..1023
            int r = idx >> 4, c = idx & 15;
            if (r < rows) {
                int gl = l0 + r;
                float4 k4, v4;
                if (gl < PAST) {
                    k4 = *(const float4*)&cache_k[cbase + (size_t)gl * 64 + c * 4];
                    v4 = *(const float4*)&cache_v[cbase + (size_t)gl * 64 + c * 4];
                    *(float4*)&out_k[obase + (size_t)gl * 64 + c * 4] = k4;
                    *(float4*)&out_v[obase + (size_t)gl * 64 + c * 4] = v4;
                } else {
                    // new rows already scattered into out_k/out_v tail
                    k4 = *(const float4*)&out_k[obase + (size_t)gl * 64 + c * 4];
                    v4 = *(const float4*)&out_v[obase + (size_t)gl * 64 + c * 4];
                }
                *(float4*)&kt[r][c * 4] = k4;
                *(float4*)&vt[r][c * 4] = v4;
            }
        }
        __syncthreads();

        // ---- scores: thread = (4 queries qg*4.., k row kp) ----
        {
            float a0 = 0.f, a1 = 0.f, a2 = 0.f, a3 = 0.f;
            #pragma unroll
            for (int c = 0; c < 16; c++) {
                float4 k4 = *(const float4*)&kt[kp][c * 4];
                float4 q0 = *(const float4*)&qs[qg * 4 + 0][c * 4];
                float4 q1 = *(const float4*)&qs[qg * 4 + 1][c * 4];
                float4 q2 = *(const float4*)&qs[qg * 4 + 2][c * 4];
                float4 q3 = *(const float4*)&qs[qg * 4 + 3][c * 4];
                a0 += k4.x*q0.x + k4.y*q0.y + k4.z*q0.z + k4.w*q0.w;
                a1 += k4.x*q1.x + k4.y*q1.y + k4.z*q1.z + k4.w*q1.w;
                a2 += k4.x*q2.x + k4.y*q2.y + k4.z*q2.z + k4.w*q2.w;
                a3 += k4.x*q3.x + k4.y*q3.y + k4.z*q3.z + k4.w*q3.w;
            }
            bool valid = kp < rows;
            ptT[qg * 4 + 0][kp] = valid ? a0 : -1e30f;
            ptT[qg * 4 + 1][kp] = valid ? a1 : -1e30f;
            ptT[qg * 4 + 2][kp] = valid ? a2 : -1e30f;
            ptT[qg * 4 + 3][kp] = valid ? a3 : -1e30f;
        }
        __syncthreads();

        // ---- softmax partial: thread = (q=pq, seg=dc) over 4 scores ----
        {
            float4 p = *(const float4*)&ptT[pq][dc * 4];
            float mt = fmaxf(fmaxf(p.x, p.y), fmaxf(p.z, p.w));
            #pragma unroll
            for (int s = 8; s >= 1; s >>= 1)
                mt = fmaxf(mt, __shfl_xor_sync(0xffffffffu, mt, s, 16));
            float mo = m_run[pq];
            float mn = fmaxf(mo, mt);
            float fc = __expf(mo - mn);
            p.x = __expf(p.x - mn); p.y = __expf(p.y - mn);
            p.z = __expf(p.z - mn); p.w = __expf(p.w - mn);
            *(float4*)&ptT[pq][dc * 4] = p;
            float ss = p.x + p.y + p.z + p.w;
            #pragma unroll
            for (int s = 8; s >= 1; s >>= 1)
                ss += __shfl_xor_sync(0xffffffffu, ss, s, 16);
            if (dc == 0) {
                m_run[pq] = mn;
                fac_s[pq] = fc;
                l_run[pq] = l_run[pq] * fc + ss;
            }
        }
        __syncthreads();

        // ---- AV: thread = (pq, dc) over `rows` values ----
        {
            float f = fac_s[pq];
            oacc.x *= f; oacc.y *= f; oacc.z *= f; oacc.w *= f;
            #pragma unroll 4
            for (int r0 = 0; r0 < rows; r0 += 4) {
                float4 p4 = *(const float4*)&ptT[pq][r0];
                float4 v0 = *(const float4*)&vt[r0 + 0][dc * 4];
                float4 v1 = *(const float4*)&vt[r0 + 1][dc * 4];
                float4 v2 = *(const float4*)&vt[r0 + 2][dc * 4];
                float4 v3 = *(const float4*)&vt[r0 + 3][dc * 4];
                oacc.x += p4.x*v0.x + p4.y*v1.x + p4.z*v2.x + p4.w*v3.x;
                oacc.y += p4.x*v0.y + p4.y*v1.y + p4.z*v2.y + p4.w*v3.y;
                oacc.z += p4.x*v0.z + p4.y*v1.z + p4.z*v2.z + p4.w*v3.z;
                oacc.w += p4.x*v0.w + p4.y*v1.w + p4.z*v2.w + p4.w*v3.w;
            }
        }
    }

    __syncthreads();
    // Write partials (un-normalized o, running m/l)
    const size_t pbase = (size_t)blockIdx.x * 1024;
    *(float4*)&g_po[pbase + pq * 64 + dc * 4] = oacc;
    if (tid < 16) {
        g_pm[blockIdx.x * 16 + tid] = m_run[tid];
        g_pl[blockIdx.x * 16 + tid] = l_run[tid];
    }
}

// ---------------------------------------------------------------------------
// Combine split partials -> g_obuf [B,S,H*hd]
// ---------------------------------------------------------------------------
__global__ __launch_bounds__(256)
void attn_reduce_kernel() {
    const int bh = blockIdx.x;
    const int tid = threadIdx.x;
    const int pq = tid >> 4, dc = tid & 15;
    const int base = bh * NSPLIT;

    float mm = -1e30f;
    #pragma unroll
    for (int s = 0; s < NSPLIT; s++)
        mm = fmaxf(mm, g_pm[(base + s) * 16 + pq]);

    float4 acc = make_float4(0.f, 0.f, 0.f, 0.f);
    float l = 0.f;
    #pragma unroll
    for (int s = 0; s < NSPLIT; s++) {
        float w = __expf(g_pm[(base + s) * 16 + pq] - mm);
        float4 o = *(const float4*)&g_po[(size_t)(base + s) * 1024 + pq * 64 + dc * 4];
        acc.x += w * o.x; acc.y += w * o.y;
        acc.z += w * o.z; acc.w += w * o.w;
        l += w * g_pl[(base + s) * 16 + pq];
    }
    float inv = 1.0f / l;
    const int b = bh >> 4, h = bh & 15;
    float4 r = make_float4(acc.x * inv, acc.y * inv, acc.z * inv, acc.w * inv);
    *(float4*)&g_obuf[(size_t)(b * 16 + pq) * D_MODEL + h * 64 + dc * 4] = r;
}

// ---------------------------------------------------------------------------
extern "C" void kernel_launch(void* const* d_in, const int* in_sizes, int n_in,
                              void* d_out, int out_size) {
    const float* x       = (const float*)d_in[0];
    const float* cache_k = (const float*)d_in[1];
    const float* cache_v = (const float*)d_in[2];
    const float* qkv_w   = (const float*)d_in[3];
    const float* qkv_b   = (const float*)d_in[4];
    const float* out_w   = (const float*)d_in[5];
    const float* out_b   = (const float*)d_in[6];

    float* out   = (float*)d_out;
    float* out_y = out + OUT_Y_OFF;
    float* out_k = out + OUT_K_OFF;
    float* out_v = out + OUT_V_OFF;

    float *qkv_p = nullptr, *obuf_p = nullptr;
    cudaGetSymbolAddress((void**)&qkv_p,  g_qkv);
    cudaGetSymbolAddress((void**)&obuf_p, g_obuf);

    // 1) QKV projection -> g_qkv [256,3072]
    gemm_bias_kernel<<<dim3(3072 / 64, M_ROWS / 64), 256>>>(
        x, qkv_w, qkv_b, qkv_p, 3072, D_MODEL);

    // 2) Append new K/V rows into out_k/out_v tails
    scatter_newkv_kernel<<<256, 256>>>(out_k, out_v);

    // 3) Fused attention + cache copy-out (split-KV x4)
    attn_split_kernel<<<B_SZ * H_SZ * NSPLIT, 256>>>(cache_k, cache_v, out_k, out_v);

    // 4) Combine splits -> g_obuf
    attn_reduce_kernel<<<B_SZ * H_SZ, 256>>>();

    // 5) Output projection -> y
    gemm_bias_kernel<<<dim3(D_MODEL / 64, M_ROWS / 64), 256>>>(
        obuf_p, out_w, out_b, out_y, D_MODEL, D_MODEL);
}